// round 5
// baseline (speedup 1.0000x reference)
#include <cuda_runtime.h>

#define NN   4096
#define BB   8
#define FIN  40
#define HH   64
#define KK   5
#define LL   4092   // N - K + 1

#define RC1  128    // row chunks, kernel 1 (32 rows each)
#define RC2  64     // row chunks, kernel 2 (64 rows each)
#define YC   32     // y chunks in k3

// ---- scratch (static device memory; every element rewritten each launch) ----
__device__ float d_Tpart[RC1][NN];          // partial column sums of A
__device__ float d_cpart[RC2][KK][NN];      // partial c_k[m]
__device__ float d_c[KK][NN];               // combined c_k[m]
__device__ float d_g[KK][NN];               // g_k[n]
__device__ float d_u[NN * FIN];             // u[m][f] = sum_k s[k][f] c_k[m]
__device__ float d_ypart[BB * YC];          // partial dot products
__device__ float d_sfk[KK][FIN];            // folded weight vector s[k][f]
__device__ float d_tk[KK];                  // t[k] = b1 . r[k]
__device__ float d_misc[2];                 // bias2, C0

// ============================================================
// Kernel 0: fold weights (independent of A, x).
// ============================================================
__global__ void k0_prep(const float* __restrict__ W1, const float* __restrict__ b1,
                        const float* __restrict__ W2, const float* __restrict__ b2,
                        const float* __restrict__ cw, const float* __restrict__ cb,
                        const float* __restrict__ fw, const float* __restrict__ fb) {
    __shared__ float q_s[HH][KK];
    __shared__ float r_s[KK][HH];
    const int t = threadIdx.x;   // 256

    for (int idx = t; idx < HH * KK; idx += 256) {
        int i = idx / KK, k = idx % KK;
        float s = 0.f;
        for (int o = 0; o < HH; o++) s += __ldg(&fw[o]) * __ldg(&cw[(o * HH + i) * KK + k]);
        q_s[i][k] = s;
    }
    __syncthreads();
    for (int idx = t; idx < KK * HH; idx += 256) {
        int k = idx / HH, h = idx % HH;
        float s = 0.f;
        for (int i = 0; i < HH; i++) s += __ldg(&W2[h * HH + i]) * q_s[i][k];
        r_s[k][h] = s;
    }
    __syncthreads();
    for (int idx = t; idx < KK * FIN; idx += 256) {
        int k = idx / FIN, f = idx % FIN;
        float s = 0.f;
        for (int h = 0; h < HH; h++) s += __ldg(&W1[f * HH + h]) * r_s[k][h];
        d_sfk[k][f] = s;
    }
    if (t < KK) {
        float s = 0.f;
        for (int h = 0; h < HH; h++) s += __ldg(&b1[h]) * r_s[t][h];
        d_tk[t] = s;
    }
    if (t == 0) {
        float bias2 = 0.f;
        for (int i = 0; i < HH; i++)
            for (int k = 0; k < KK; k++) bias2 += q_s[i][k] * __ldg(&b2[i]);
        float C0 = __ldg(&fb[0]);
        for (int o = 0; o < HH; o++) C0 += __ldg(&fw[o]) * __ldg(&cb[o]);
        d_misc[0] = bias2;
        d_misc[1] = C0;
    }
}

// ============================================================
// Kernel 1: partial column sums of A.  Tpart[rc][m] = sum of 32 rows.
// grid (4, 128) = 512 blocks x 256 threads, float4 loads.
// ============================================================
__global__ void k1_colsum(const float* __restrict__ A) {
    const int c4 = blockIdx.x * 256 + threadIdx.x;   // float4 col index
    const int n0 = blockIdx.y * (NN / RC1);          // 32-row chunk
    const float4* Ap = reinterpret_cast<const float4*>(A);
    float4 acc = make_float4(0.f, 0.f, 0.f, 0.f);
#pragma unroll 8
    for (int n = n0; n < n0 + NN / RC1; n++) {
        float4 a = __ldg(&Ap[n * (NN / 4) + c4]);
        acc.x += a.x; acc.y += a.y; acc.z += a.z; acc.w += a.w;
    }
    *reinterpret_cast<float4*>(&d_Tpart[blockIdx.y][c4 * 4]) = acc;
}

// ============================================================
// Kernel 2: fused g + c partials.
// grid (4, 64) = 256 blocks x 256 threads; 64-row strip per block.
// All 256 threads cooperate on the Tpart combine (4 r-groups x 64 n).
// ============================================================
__global__ void k2_cpart(const float* __restrict__ A) {
    __shared__ float gsk[KK][64];
    __shared__ float tred[4][64];
    const int tid = threadIdx.x;
    const int c4  = blockIdx.x * 256 + tid;          // float4 col index
    const int n0  = blockIdx.y * 64;

    // --- cooperative Tpart combine: rg-group sums 32 of 128 partials ---
    {
        const int rg = tid >> 6;          // 0..3
        const int nl = tid & 63;
        float T = 0.f;
#pragma unroll
        for (int r = rg * 32; r < rg * 32 + 32; r++) T += d_Tpart[r][n0 + nl];
        tred[rg][nl] = T;
    }
    __syncthreads();

    if (tid < 64) {
        const int n = n0 + tid;
        float T = tred[0][tid] + tred[1][tid] + tred[2][tid] + tred[3][tid];

        float top[4], bot[4];
#pragma unroll
        for (int j = 0; j < 4; j++) top[j] = __ldg(&A[j * NN + n]);
#pragma unroll
        for (int j = 0; j < 4; j++) bot[j] = __ldg(&A[(4092 + j) * NN + n]);

        float cumtop = 0.f;
#pragma unroll
        for (int k = 0; k < KK; k++) {
            float sb = 0.f;
#pragma unroll
            for (int j = 0; j < 4; j++) if (j >= k) sb += bot[j];
            float g = T - cumtop - sb;
            gsk[k][tid] = g;
            if (blockIdx.x == 0) d_g[k][n] = g;
            if (k < 4) cumtop += top[k];
        }
    }
    __syncthreads();

    // --- main accumulation over the 64-row strip ---
    float4 acc[KK];
#pragma unroll
    for (int k = 0; k < KK; k++) acc[k] = make_float4(0.f, 0.f, 0.f, 0.f);

    const float4* Ap = reinterpret_cast<const float4*>(A);
#pragma unroll 8
    for (int nl = 0; nl < 64; nl++) {
        float4 a = __ldg(&Ap[(n0 + nl) * (NN / 4) + c4]);
        float g0 = gsk[0][nl], g1 = gsk[1][nl], g2 = gsk[2][nl];
        float g3 = gsk[3][nl], g4 = gsk[4][nl];
        acc[0].x += a.x * g0; acc[0].y += a.y * g0; acc[0].z += a.z * g0; acc[0].w += a.w * g0;
        acc[1].x += a.x * g1; acc[1].y += a.y * g1; acc[1].z += a.z * g1; acc[1].w += a.w * g1;
        acc[2].x += a.x * g2; acc[2].y += a.y * g2; acc[2].z += a.z * g2; acc[2].w += a.w * g2;
        acc[3].x += a.x * g3; acc[3].y += a.y * g3; acc[3].z += a.z * g3; acc[3].w += a.w * g3;
        acc[4].x += a.x * g4; acc[4].y += a.y * g4; acc[4].z += a.z * g4; acc[4].w += a.w * g4;
    }
#pragma unroll
    for (int k = 0; k < KK; k++)
        *reinterpret_cast<float4*>(&d_cpart[blockIdx.y][k][c4 * 4]) = acc[k];
}

// ============================================================
// Kernel 2b: combine c partials.  One thread per (k,m) = 20480 threads.
// grid 80 blocks x 256 threads; 64 independent unrolled loads per thread.
// ============================================================
__global__ void k2b_combine() {
    const int idx = blockIdx.x * 256 + threadIdx.x;   // 0 .. KK*NN-1
    const int k = idx / NN;
    const int m = idx % NN;
    float s = 0.f;
#pragma unroll
    for (int r = 0; r < RC2; r++) s += d_cpart[r][k][m];
    d_c[k][m] = s;
}

// ============================================================
// Kernel 2c: build u[m][f] = sum_k s[k][f] c_k[m].
// One thread per (m, f4) = 40960 threads; grid 160 x 256.
// ============================================================
__global__ void k2c_build_u() {
    __shared__ float s_sh[KK][FIN];
    const int t = threadIdx.x;
    for (int idx = t; idx < KK * FIN; idx += 256)
        s_sh[idx / FIN][idx % FIN] = d_sfk[idx / FIN][idx % FIN];
    __syncthreads();

    const int idx = blockIdx.x * 256 + t;   // 0 .. NN*10-1
    const int m  = idx / (FIN / 4);
    const int f4 = idx % (FIN / 4);

    float c[KK];
#pragma unroll
    for (int k = 0; k < KK; k++) c[k] = d_c[k][m];

    float4 u = make_float4(0.f, 0.f, 0.f, 0.f);
#pragma unroll
    for (int k = 0; k < KK; k++) {
        float ck = c[k];
        u.x += ck * s_sh[k][f4 * 4 + 0];
        u.y += ck * s_sh[k][f4 * 4 + 1];
        u.z += ck * s_sh[k][f4 * 4 + 2];
        u.w += ck * s_sh[k][f4 * 4 + 3];
    }
    reinterpret_cast<float4*>(d_u)[idx] = u;
}

// ============================================================
// Kernel 3: y[b] partials = x[b] . u   (element-wise dot, float4).
// grid (YC, BB) = 256 blocks x 256 threads; 5 float4 per thread.
// ============================================================
__global__ void k3_dot(const float* __restrict__ x) {
    const int b  = blockIdx.y;
    const int mc = blockIdx.x;
    const int t  = threadIdx.x;
    const int ub4 = mc * (NN * FIN / YC) / 4;
    const float4* xp = reinterpret_cast<const float4*>(x) + (size_t)b * (NN * FIN / 4) + ub4;
    const float4* up = reinterpret_cast<const float4*>(d_u) + ub4;

    float acc = 0.f;
#pragma unroll
    for (int i = 0; i < (NN * FIN / YC) / 4 / 256; i++) {      // 5 iters
        float4 xv = __ldg(&xp[i * 256 + t]);
        float4 uv = __ldg(&up[i * 256 + t]);
        acc += xv.x * uv.x + xv.y * uv.y + xv.z * uv.z + xv.w * uv.w;
    }

    __shared__ float red[256];
    red[t] = acc;
    __syncthreads();
    for (int ofs = 128; ofs > 0; ofs >>= 1) {
        if (t < ofs) red[t] += red[t + ofs];
        __syncthreads();
    }
    if (t == 0) d_ypart[b * YC + mc] = red[0];
}

// ============================================================
// Kernel 4: final fold.
// ============================================================
__global__ void k4_final(float* __restrict__ out) {
    __shared__ float red[256];
    __shared__ float sg_s[KK];
    const int t = threadIdx.x;   // 256

    float part[KK] = {0.f, 0.f, 0.f, 0.f, 0.f};
    for (int m = t; m < NN; m += 256) {
#pragma unroll
        for (int k = 0; k < KK; k++) part[k] += d_g[k][m];
    }
    for (int k = 0; k < KK; k++) {
        red[t] = part[k];
        __syncthreads();
        for (int ofs = 128; ofs > 0; ofs >>= 1) {
            if (t < ofs) red[t] += red[t + ofs];
            __syncthreads();
        }
        if (t == 0) sg_s[k] = red[0];
        __syncthreads();
    }

    if (t < BB) {
        float y = 0.f;
#pragma unroll
        for (int mc = 0; mc < YC; mc++) y += d_ypart[t * YC + mc];
        float gt = 0.f;
#pragma unroll
        for (int k = 0; k < KK; k++) gt += sg_s[k] * d_tk[k];
        out[t] = (y + gt) * (1.0f / (float)LL) + d_misc[0] + d_misc[1];
    }
}

// ============================================================
extern "C" void kernel_launch(void* const* d_in, const int* in_sizes, int n_in,
                              void* d_out, int out_size) {
    const float* x   = (const float*)d_in[0];
    const float* A   = (const float*)d_in[1];
    const float* W1  = (const float*)d_in[2];
    const float* b1  = (const float*)d_in[3];
    const float* W2  = (const float*)d_in[4];
    const float* b2  = (const float*)d_in[5];
    const float* cw  = (const float*)d_in[6];
    const float* cb  = (const float*)d_in[7];
    const float* fw  = (const float*)d_in[8];
    const float* fb  = (const float*)d_in[9];
    float* out = (float*)d_out;

    k0_prep<<<1, 256>>>(W1, b1, W2, b2, cw, cb, fw, fb);
    k1_colsum<<<dim3(4, RC1), 256>>>(A);
    k2_cpart<<<dim3(4, 64), 256>>>(A);
    k2b_combine<<<80, 256>>>();
    k2c_build_u<<<160, 256>>>();
    k3_dot<<<dim3(YC, BB), 256>>>(x);
    k4_final<<<1, 256>>>(out);
}

// round 6
// speedup vs baseline: 1.1333x; 1.1333x over previous
#include <cuda_runtime.h>

#define NN   4096
#define BB   8
#define FIN  40
#define HH   64
#define KK   5
#define LL   4092   // N - K + 1

#define RC1  128    // row chunks for colsum (32 rows each)
#define RC2  32     // row strips in kB (128 rows each)
#define NCB  128    // kC blocks (32 m each)

// ---- scratch (static device memory; every element rewritten each launch) ----
__device__ float d_Tpart[RC1][NN];          // partial column sums of A
__device__ float d_cpart[RC2][KK][NN];      // partial c_k[m]
__device__ float d_g[KK][NN];               // g_k[n]
__device__ float d_xt[BB * NN * 8];         // X~[b][m][k] (k padded to 8)
__device__ float d_ypart[BB * NCB];         // partial dot products
__device__ float d_tk[KK];                  // t[k] = b1 . r[k]
__device__ float d_misc[2];                 // bias2, C0

// ---- shared weight-fold helper (redundant per block; ~54k FMA total) ----
__device__ __forceinline__ void fold_weights(
    const float* __restrict__ W2, const float* __restrict__ cw,
    const float* __restrict__ fw,
    float (&q_s)[HH][KK], float (&r_s)[KK][HH], int t)
{
    for (int idx = t; idx < HH * KK; idx += 256) {
        int i = idx / KK, k = idx % KK;
        float s = 0.f;
        for (int o = 0; o < HH; o++) s += __ldg(&fw[o]) * __ldg(&cw[(o * HH + i) * KK + k]);
        q_s[i][k] = s;
    }
    __syncthreads();
    for (int idx = t; idx < KK * HH; idx += 256) {
        int k = idx / HH, h = idx % HH;
        float s = 0.f;
        for (int i = 0; i < HH; i++) s += __ldg(&W2[h * HH + i]) * q_s[i][k];
        r_s[k][h] = s;
    }
    __syncthreads();
}

// ============================================================
// Kernel A: 577 blocks x 256 threads.
//   blocks [0,512): partial column sums of A (32 rows each)
//   blocks [512,576): X~[b][m][k] = sum_f x[b][m][f] * s[k][f]
//                     (weights folded redundantly per block)
//   block 576: t_k, bias2, C0
// ============================================================
__global__ void __launch_bounds__(256) kA(
    const float* __restrict__ A, const float* __restrict__ x,
    const float* __restrict__ W1, const float* __restrict__ b1,
    const float* __restrict__ W2, const float* __restrict__ b2,
    const float* __restrict__ cw, const float* __restrict__ cb,
    const float* __restrict__ fw, const float* __restrict__ fb)
{
    const int bid = blockIdx.x;
    const int t   = threadIdx.x;

    if (bid < 512) {
        // ---- column-sum partials ----
        const int c4 = (bid & 3) * 256 + t;          // float4 col index
        const int n0 = (bid >> 2) * 32;
        const float4* Ap = reinterpret_cast<const float4*>(A);
        float4 acc = make_float4(0.f, 0.f, 0.f, 0.f);
#pragma unroll 8
        for (int n = n0; n < n0 + 32; n++) {
            float4 a = __ldg(&Ap[n * (NN / 4) + c4]);
            acc.x += a.x; acc.y += a.y; acc.z += a.z; acc.w += a.w;
        }
        *reinterpret_cast<float4*>(&d_Tpart[bid >> 2][c4 * 4]) = acc;
        return;
    }

    __shared__ float q_s[HH][KK];
    __shared__ float r_s[KK][HH];
    fold_weights(W2, cw, fw, q_s, r_s, t);

    if (bid < 576) {
        // ---- X~ blocks ----
        __shared__ float s_s[KK][FIN];
        for (int idx = t; idx < KK * FIN; idx += 256) {
            int k = idx / FIN, f = idx % FIN;
            float s = 0.f;
            for (int h = 0; h < HH; h++) s += __ldg(&W1[f * HH + h]) * r_s[k][h];
            s_s[k][f] = s;
        }
        __syncthreads();

        const int bid2 = bid - 512;                  // 0..63
#pragma unroll
        for (int j = 0; j < 2; j++) {
            const int gr = bid2 * 512 + j * 256 + t; // global (b,m) row, 0..32767
            const float4* xp = reinterpret_cast<const float4*>(x) + (size_t)gr * (FIN / 4);
            float d0 = 0.f, d1 = 0.f, d2 = 0.f, d3 = 0.f, d4 = 0.f;
#pragma unroll
            for (int f4 = 0; f4 < FIN / 4; f4++) {
                float4 xv = __ldg(&xp[f4]);
                d0 += xv.x * s_s[0][f4*4] + xv.y * s_s[0][f4*4+1] + xv.z * s_s[0][f4*4+2] + xv.w * s_s[0][f4*4+3];
                d1 += xv.x * s_s[1][f4*4] + xv.y * s_s[1][f4*4+1] + xv.z * s_s[1][f4*4+2] + xv.w * s_s[1][f4*4+3];
                d2 += xv.x * s_s[2][f4*4] + xv.y * s_s[2][f4*4+1] + xv.z * s_s[2][f4*4+2] + xv.w * s_s[2][f4*4+3];
                d3 += xv.x * s_s[3][f4*4] + xv.y * s_s[3][f4*4+1] + xv.z * s_s[3][f4*4+2] + xv.w * s_s[3][f4*4+3];
                d4 += xv.x * s_s[4][f4*4] + xv.y * s_s[4][f4*4+1] + xv.z * s_s[4][f4*4+2] + xv.w * s_s[4][f4*4+3];
            }
            float4* xt = reinterpret_cast<float4*>(&d_xt[(size_t)gr * 8]);
            xt[0] = make_float4(d0, d1, d2, d3);
            xt[1] = make_float4(d4, 0.f, 0.f, 0.f);
        }
        return;
    }

    // ---- misc block ----
    if (t < KK) {
        float s = 0.f;
        for (int h = 0; h < HH; h++) s += __ldg(&b1[h]) * r_s[t][h];
        d_tk[t] = s;
    }
    if (t == 0) {
        float bias2 = 0.f;
        for (int i = 0; i < HH; i++)
            for (int k = 0; k < KK; k++) bias2 += q_s[i][k] * __ldg(&b2[i]);
        float C0 = __ldg(&fb[0]);
        for (int o = 0; o < HH; o++) C0 += __ldg(&fw[o]) * __ldg(&cb[o]);
        d_misc[0] = bias2;
        d_misc[1] = C0;
    }
}

// ============================================================
// Kernel B: fused g + c partials over 128-row strips.
// grid (4, 32) = 128 blocks x 256 threads.
// ============================================================
__global__ void __launch_bounds__(256) kB(const float* __restrict__ A) {
    __shared__ float gsk[KK][128];
    __shared__ float tred[2][128];
    const int tid = threadIdx.x;
    const int c4  = blockIdx.x * 256 + tid;          // float4 col index
    const int n0  = blockIdx.y * 128;

    // cooperative Tpart combine: 2 r-groups x 128 n
    {
        const int rg = tid >> 7;          // 0..1
        const int nl = tid & 127;
        float T = 0.f;
#pragma unroll
        for (int r = rg * 64; r < rg * 64 + 64; r++) T += d_Tpart[r][n0 + nl];
        tred[rg][nl] = T;
    }
    __syncthreads();

    if (tid < 128) {
        const int n = n0 + tid;
        float T = tred[0][tid] + tred[1][tid];

        float top[4], bot[4];
#pragma unroll
        for (int j = 0; j < 4; j++) top[j] = __ldg(&A[j * NN + n]);
#pragma unroll
        for (int j = 0; j < 4; j++) bot[j] = __ldg(&A[(4092 + j) * NN + n]);

        float cumtop = 0.f;
#pragma unroll
        for (int k = 0; k < KK; k++) {
            float sb = 0.f;
#pragma unroll
            for (int j = 0; j < 4; j++) if (j >= k) sb += bot[j];
            float g = T - cumtop - sb;
            gsk[k][tid] = g;
            if (blockIdx.x == 0) d_g[k][n] = g;
            if (k < 4) cumtop += top[k];
        }
    }
    __syncthreads();

    float4 acc[KK];
#pragma unroll
    for (int k = 0; k < KK; k++) acc[k] = make_float4(0.f, 0.f, 0.f, 0.f);

    const float4* Ap = reinterpret_cast<const float4*>(A);
#pragma unroll 8
    for (int nl = 0; nl < 128; nl++) {
        float4 a = __ldg(&Ap[(n0 + nl) * (NN / 4) + c4]);
        float g0 = gsk[0][nl], g1 = gsk[1][nl], g2 = gsk[2][nl];
        float g3 = gsk[3][nl], g4 = gsk[4][nl];
        acc[0].x += a.x * g0; acc[0].y += a.y * g0; acc[0].z += a.z * g0; acc[0].w += a.w * g0;
        acc[1].x += a.x * g1; acc[1].y += a.y * g1; acc[1].z += a.z * g1; acc[1].w += a.w * g1;
        acc[2].x += a.x * g2; acc[2].y += a.y * g2; acc[2].z += a.z * g2; acc[2].w += a.w * g2;
        acc[3].x += a.x * g3; acc[3].y += a.y * g3; acc[3].z += a.z * g3; acc[3].w += a.w * g3;
        acc[4].x += a.x * g4; acc[4].y += a.y * g4; acc[4].z += a.z * g4; acc[4].w += a.w * g4;
    }
#pragma unroll
    for (int k = 0; k < KK; k++)
        *reinterpret_cast<float4*>(&d_cpart[blockIdx.y][k][c4 * 4]) = acc[k];
}

// ============================================================
// Kernel C: combine c over its 32-m slice, dot with X~ for all b.
// grid NCB=128 x 256 threads.
// ============================================================
__global__ void __launch_bounds__(256) kC() {
    __shared__ float4 part[40][4];    // (k,m4) x r-group partials
    __shared__ float  c_s[KK][32];
    const int t  = threadIdx.x;
    const int m0 = blockIdx.x * 32;

    // combine: 160 threads, each 8 float4 loads
    if (t < 160) {
        const int r4  = t & 3;          // r-group (8 partials)
        const int col = t >> 2;         // 0..39: k = col/8, m4 = col%8
        const int k   = col >> 3;
        const int m4  = col & 7;
        float4 s = make_float4(0.f, 0.f, 0.f, 0.f);
#pragma unroll
        for (int r = r4 * 8; r < r4 * 8 + 8; r++) {
            float4 v = *reinterpret_cast<const float4*>(&d_cpart[r][k][m0 + m4 * 4]);
            s.x += v.x; s.y += v.y; s.z += v.z; s.w += v.w;
        }
        part[col][r4] = s;
    }
    __syncthreads();
    if (t < 40) {
        const int k  = t >> 3;
        const int m4 = t & 7;
        float4 s0 = part[t][0], s1 = part[t][1], s2 = part[t][2], s3 = part[t][3];
        c_s[k][m4 * 4 + 0] = s0.x + s1.x + s2.x + s3.x;
        c_s[k][m4 * 4 + 1] = s0.y + s1.y + s2.y + s3.y;
        c_s[k][m4 * 4 + 2] = s0.z + s1.z + s2.z + s3.z;
        c_s[k][m4 * 4 + 3] = s0.w + s1.w + s2.w + s3.w;
    }
    __syncthreads();

    // dot: thread = (b, ml); warp w == batch b
    const int b  = t >> 5;
    const int ml = t & 31;
    const int gr = b * NN + m0 + ml;
    const float4* xt = reinterpret_cast<const float4*>(&d_xt[(size_t)gr * 8]);
    float4 x0 = __ldg(&xt[0]);
    float4 x1 = __ldg(&xt[1]);
    float v = x0.x * c_s[0][ml] + x0.y * c_s[1][ml] + x0.z * c_s[2][ml]
            + x0.w * c_s[3][ml] + x1.x * c_s[4][ml];
#pragma unroll
    for (int ofs = 16; ofs > 0; ofs >>= 1)
        v += __shfl_down_sync(0xffffffffu, v, ofs);
    if (ml == 0) d_ypart[b * NCB + blockIdx.x] = v;
}

// ============================================================
// Kernel D: final fold. 1 block x 256 threads.
// ============================================================
__global__ void __launch_bounds__(256) kD(float* __restrict__ out) {
    __shared__ float red[256];
    __shared__ float sg_s[KK];
    __shared__ float y_s[BB];
    const int t = threadIdx.x;

    // sg_k = sum_n g_k[n]
    float part[KK] = {0.f, 0.f, 0.f, 0.f, 0.f};
    for (int m = t; m < NN; m += 256) {
#pragma unroll
        for (int k = 0; k < KK; k++) part[k] += d_g[k][m];
    }
    for (int k = 0; k < KK; k++) {
        red[t] = part[k];
        __syncthreads();
        for (int ofs = 128; ofs > 0; ofs >>= 1) {
            if (t < ofs) red[t] += red[t + ofs];
            __syncthreads();
        }
        if (t == 0) sg_s[k] = red[0];
        __syncthreads();
    }

    // y[b]: warp b sums its 128 partials
    {
        const int b    = t >> 5;
        const int lane = t & 31;
        float v = 0.f;
#pragma unroll
        for (int j = 0; j < NCB / 32; j++) v += d_ypart[b * NCB + lane + j * 32];
#pragma unroll
        for (int ofs = 16; ofs > 0; ofs >>= 1)
            v += __shfl_down_sync(0xffffffffu, v, ofs);
        if (lane == 0) y_s[b] = v;
    }
    __syncthreads();

    if (t < BB) {
        float gt = 0.f;
#pragma unroll
        for (int k = 0; k < KK; k++) gt += sg_s[k] * d_tk[k];
        out[t] = (y_s[t] + gt) * (1.0f / (float)LL) + d_misc[0] + d_misc[1];
    }
}

// ============================================================
extern "C" void kernel_launch(void* const* d_in, const int* in_sizes, int n_in,
                              void* d_out, int out_size) {
    const float* x   = (const float*)d_in[0];
    const float* A   = (const float*)d_in[1];
    const float* W1  = (const float*)d_in[2];
    const float* b1  = (const float*)d_in[3];
    const float* W2  = (const float*)d_in[4];
    const float* b2  = (const float*)d_in[5];
    const float* cw  = (const float*)d_in[6];
    const float* cb  = (const float*)d_in[7];
    const float* fw  = (const float*)d_in[8];
    const float* fb  = (const float*)d_in[9];
    float* out = (float*)d_out;

    kA<<<577, 256>>>(A, x, W1, b1, W2, b2, cw, cb, fw, fb);
    kB<<<dim3(4, RC2), 256>>>(A);
    kC<<<NCB, 256>>>();
    kD<<<1, 256>>>(out);
}

// round 7
// speedup vs baseline: 1.2405x; 1.0946x over previous
#include <cuda_runtime.h>

#define NN   4096
#define BB   8
#define FIN  40
#define HH   64
#define KK   5
#define LL   4092   // N - K + 1

#define RC1  128    // row chunks for colsum (32 rows each)
#define RC2  32     // row strips in kB (128 rows each)
#define NCB  128    // kC blocks (32 m each)

// ---- scratch (static device memory; every element rewritten each launch) ----
__device__ float d_Tpart[RC1][NN];          // partial column sums of A
__device__ float d_cpart[RC2][KK][NN];      // partial c_k[m]
__device__ float d_sgpart[RC2][KK];         // per-strip partial sums of g
__device__ float d_xt[BB * NN * 8];         // X~[b][m][k] (k padded to 8)
__device__ float d_ypart[BB * NCB];         // partial dot products
__device__ float d_tk[KK];                  // t[k] = b1 . r[k]
__device__ float d_misc[2];                 // bias2, C0

// ---- shared weight-fold helper (redundant per block; ~54k FMA total) ----
__device__ __forceinline__ void fold_weights(
    const float* __restrict__ W2, const float* __restrict__ cw,
    const float* __restrict__ fw,
    float (&q_s)[HH][KK], float (&r_s)[KK][HH], int t)
{
    for (int idx = t; idx < HH * KK; idx += 256) {
        int i = idx / KK, k = idx % KK;
        float s = 0.f;
        for (int o = 0; o < HH; o++) s += __ldg(&fw[o]) * __ldg(&cw[(o * HH + i) * KK + k]);
        q_s[i][k] = s;
    }
    __syncthreads();
    for (int idx = t; idx < KK * HH; idx += 256) {
        int k = idx / HH, h = idx % HH;
        float s = 0.f;
        for (int i = 0; i < HH; i++) s += __ldg(&W2[h * HH + i]) * q_s[i][k];
        r_s[k][h] = s;
    }
    __syncthreads();
}

// ============================================================
// Kernel A: 577 blocks x 256 threads.
//   blocks [0,512): partial column sums of A (32 rows each)
//   blocks [512,576): X~[b][m][k] = sum_f x[b][m][f] * s[k][f]
//   block 576: t_k, bias2, C0
// ============================================================
__global__ void __launch_bounds__(256) kA(
    const float* __restrict__ A, const float* __restrict__ x,
    const float* __restrict__ W1, const float* __restrict__ b1,
    const float* __restrict__ W2, const float* __restrict__ b2,
    const float* __restrict__ cw, const float* __restrict__ cb,
    const float* __restrict__ fw, const float* __restrict__ fb)
{
    const int bid = blockIdx.x;
    const int t   = threadIdx.x;

    if (bid < 512) {
        // ---- column-sum partials ----
        const int c4 = (bid & 3) * 256 + t;          // float4 col index
        const int n0 = (bid >> 2) * 32;
        const float4* Ap = reinterpret_cast<const float4*>(A);
        float4 acc = make_float4(0.f, 0.f, 0.f, 0.f);
#pragma unroll 8
        for (int n = n0; n < n0 + 32; n++) {
            float4 a = __ldg(&Ap[n * (NN / 4) + c4]);
            acc.x += a.x; acc.y += a.y; acc.z += a.z; acc.w += a.w;
        }
        *reinterpret_cast<float4*>(&d_Tpart[bid >> 2][c4 * 4]) = acc;
        return;
    }

    __shared__ float q_s[HH][KK];
    __shared__ float r_s[KK][HH];
    fold_weights(W2, cw, fw, q_s, r_s, t);

    if (bid < 576) {
        // ---- X~ blocks ----
        __shared__ float s_s[KK][FIN];
        for (int idx = t; idx < KK * FIN; idx += 256) {
            int k = idx / FIN, f = idx % FIN;
            float s = 0.f;
            for (int h = 0; h < HH; h++) s += __ldg(&W1[f * HH + h]) * r_s[k][h];
            s_s[k][f] = s;
        }
        __syncthreads();

        const int bid2 = bid - 512;                  // 0..63
#pragma unroll
        for (int j = 0; j < 2; j++) {
            const int gr = bid2 * 512 + j * 256 + t; // global (b,m) row, 0..32767
            const float4* xp = reinterpret_cast<const float4*>(x) + (size_t)gr * (FIN / 4);
            float d0 = 0.f, d1 = 0.f, d2 = 0.f, d3 = 0.f, d4 = 0.f;
#pragma unroll
            for (int f4 = 0; f4 < FIN / 4; f4++) {
                float4 xv = __ldg(&xp[f4]);
                d0 += xv.x * s_s[0][f4*4] + xv.y * s_s[0][f4*4+1] + xv.z * s_s[0][f4*4+2] + xv.w * s_s[0][f4*4+3];
                d1 += xv.x * s_s[1][f4*4] + xv.y * s_s[1][f4*4+1] + xv.z * s_s[1][f4*4+2] + xv.w * s_s[1][f4*4+3];
                d2 += xv.x * s_s[2][f4*4] + xv.y * s_s[2][f4*4+1] + xv.z * s_s[2][f4*4+2] + xv.w * s_s[2][f4*4+3];
                d3 += xv.x * s_s[3][f4*4] + xv.y * s_s[3][f4*4+1] + xv.z * s_s[3][f4*4+2] + xv.w * s_s[3][f4*4+3];
                d4 += xv.x * s_s[4][f4*4] + xv.y * s_s[4][f4*4+1] + xv.z * s_s[4][f4*4+2] + xv.w * s_s[4][f4*4+3];
            }
            float4* xt = reinterpret_cast<float4*>(&d_xt[(size_t)gr * 8]);
            xt[0] = make_float4(d0, d1, d2, d3);
            xt[1] = make_float4(d4, 0.f, 0.f, 0.f);
        }
        return;
    }

    // ---- misc block ----
    if (t < KK) {
        float s = 0.f;
        for (int h = 0; h < HH; h++) s += __ldg(&b1[h]) * r_s[t][h];
        d_tk[t] = s;
    }
    if (t == 0) {
        float bias2 = 0.f;
        for (int i = 0; i < HH; i++)
            for (int k = 0; k < KK; k++) bias2 += q_s[i][k] * __ldg(&b2[i]);
        float C0 = __ldg(&fb[0]);
        for (int o = 0; o < HH; o++) C0 += __ldg(&fw[o]) * __ldg(&cb[o]);
        d_misc[0] = bias2;
        d_misc[1] = C0;
    }
}

// ============================================================
// Kernel B: fused g + c partials over 128-row strips.
// grid (4, 32) = 128 blocks x 256 threads.
// Column-block 0 also writes per-strip sg partials (warp-0 tree).
// ============================================================
__global__ void __launch_bounds__(256) kB(const float* __restrict__ A) {
    __shared__ float gsk[KK][128];
    __shared__ float tred[2][128];
    const int tid = threadIdx.x;
    const int c4  = blockIdx.x * 256 + tid;          // float4 col index
    const int n0  = blockIdx.y * 128;

    // cooperative Tpart combine: 2 r-groups x 128 n
    {
        const int rg = tid >> 7;          // 0..1
        const int nl = tid & 127;
        float T = 0.f;
#pragma unroll
        for (int r = rg * 64; r < rg * 64 + 64; r++) T += d_Tpart[r][n0 + nl];
        tred[rg][nl] = T;
    }
    __syncthreads();

    if (tid < 128) {
        const int n = n0 + tid;
        float T = tred[0][tid] + tred[1][tid];

        float top[4], bot[4];
#pragma unroll
        for (int j = 0; j < 4; j++) top[j] = __ldg(&A[j * NN + n]);
#pragma unroll
        for (int j = 0; j < 4; j++) bot[j] = __ldg(&A[(4092 + j) * NN + n]);

        float cumtop = 0.f;
#pragma unroll
        for (int k = 0; k < KK; k++) {
            float sb = 0.f;
#pragma unroll
            for (int j = 0; j < 4; j++) if (j >= k) sb += bot[j];
            float g = T - cumtop - sb;
            gsk[k][tid] = g;
            if (k < 4) cumtop += top[k];
        }
    }
    __syncthreads();

    // per-strip sg partials (column-block 0, warp 0 only)
    if (blockIdx.x == 0 && tid < 32) {
#pragma unroll
        for (int k = 0; k < KK; k++) {
            float v = gsk[k][tid] + gsk[k][tid + 32] + gsk[k][tid + 64] + gsk[k][tid + 96];
#pragma unroll
            for (int ofs = 16; ofs > 0; ofs >>= 1)
                v += __shfl_down_sync(0xffffffffu, v, ofs);
            if (tid == 0) d_sgpart[blockIdx.y][k] = v;
        }
    }

    float4 acc[KK];
#pragma unroll
    for (int k = 0; k < KK; k++) acc[k] = make_float4(0.f, 0.f, 0.f, 0.f);

    const float4* Ap = reinterpret_cast<const float4*>(A);
#pragma unroll 8
    for (int nl = 0; nl < 128; nl++) {
        float4 a = __ldg(&Ap[(n0 + nl) * (NN / 4) + c4]);
        float g0 = gsk[0][nl], g1 = gsk[1][nl], g2 = gsk[2][nl];
        float g3 = gsk[3][nl], g4 = gsk[4][nl];
        acc[0].x += a.x * g0; acc[0].y += a.y * g0; acc[0].z += a.z * g0; acc[0].w += a.w * g0;
        acc[1].x += a.x * g1; acc[1].y += a.y * g1; acc[1].z += a.z * g1; acc[1].w += a.w * g1;
        acc[2].x += a.x * g2; acc[2].y += a.y * g2; acc[2].z += a.z * g2; acc[2].w += a.w * g2;
        acc[3].x += a.x * g3; acc[3].y += a.y * g3; acc[3].z += a.z * g3; acc[3].w += a.w * g3;
        acc[4].x += a.x * g4; acc[4].y += a.y * g4; acc[4].z += a.z * g4; acc[4].w += a.w * g4;
    }
#pragma unroll
    for (int k = 0; k < KK; k++)
        *reinterpret_cast<float4*>(&d_cpart[blockIdx.y][k][c4 * 4]) = acc[k];
}

// ============================================================
// Kernel C: combine c over its 32-m slice, dot with X~ for all b.
// grid NCB=128 x 256 threads.
// ============================================================
__global__ void __launch_bounds__(256) kC() {
    __shared__ float4 part[40][4];    // (k,m4) x r-group partials
    __shared__ float  c_s[KK][32];
    const int t  = threadIdx.x;
    const int m0 = blockIdx.x * 32;

    // combine: 160 threads, each 8 float4 loads
    if (t < 160) {
        const int r4  = t & 3;          // r-group (8 partials)
        const int col = t >> 2;         // 0..39: k = col/8, m4 = col%8
        const int k   = col >> 3;
        const int m4  = col & 7;
        float4 s = make_float4(0.f, 0.f, 0.f, 0.f);
#pragma unroll
        for (int r = r4 * 8; r < r4 * 8 + 8; r++) {
            float4 v = *reinterpret_cast<const float4*>(&d_cpart[r][k][m0 + m4 * 4]);
            s.x += v.x; s.y += v.y; s.z += v.z; s.w += v.w;
        }
        part[col][r4] = s;
    }
    __syncthreads();
    if (t < 40) {
        const int k  = t >> 3;
        const int m4 = t & 7;
        float4 s0 = part[t][0], s1 = part[t][1], s2 = part[t][2], s3 = part[t][3];
        c_s[k][m4 * 4 + 0] = s0.x + s1.x + s2.x + s3.x;
        c_s[k][m4 * 4 + 1] = s0.y + s1.y + s2.y + s3.y;
        c_s[k][m4 * 4 + 2] = s0.z + s1.z + s2.z + s3.z;
        c_s[k][m4 * 4 + 3] = s0.w + s1.w + s2.w + s3.w;
    }
    __syncthreads();

    // dot: thread = (b, ml); warp w == batch b
    const int b  = t >> 5;
    const int ml = t & 31;
    const int gr = b * NN + m0 + ml;
    const float4* xt = reinterpret_cast<const float4*>(&d_xt[(size_t)gr * 8]);
    float4 x0 = __ldg(&xt[0]);
    float4 x1 = __ldg(&xt[1]);
    float v = x0.x * c_s[0][ml] + x0.y * c_s[1][ml] + x0.z * c_s[2][ml]
            + x0.w * c_s[3][ml] + x1.x * c_s[4][ml];
#pragma unroll
    for (int ofs = 16; ofs > 0; ofs >>= 1)
        v += __shfl_down_sync(0xffffffffu, v, ofs);
    if (ml == 0) d_ypart[b * NCB + blockIdx.x] = v;
}

// ============================================================
// Kernel D: tiny epilogue. 1 block x 256 threads.
// Reads 160 sg partials + 1024 ypart + tk + misc.
// ============================================================
__global__ void __launch_bounds__(256) kD(float* __restrict__ out) {
    __shared__ float sg_s[KK];
    __shared__ float y_s[BB];
    const int t = threadIdx.x;

    // sg_k: warps 0..4, one per k, 32 strips each
    if (t < KK * 32) {
        const int k    = t >> 5;
        const int lane = t & 31;
        float v = d_sgpart[lane][k];
#pragma unroll
        for (int ofs = 16; ofs > 0; ofs >>= 1)
            v += __shfl_down_sync(0xffffffffu, v, ofs);
        if (lane == 0) sg_s[k] = v;
    }
    __syncthreads();

    // y[b]: warp b sums its 128 partials
    {
        const int b    = t >> 5;
        const int lane = t & 31;
        float v = 0.f;
#pragma unroll
        for (int j = 0; j < NCB / 32; j++) v += d_ypart[b * NCB + lane + j * 32];
#pragma unroll
        for (int ofs = 16; ofs > 0; ofs >>= 1)
            v += __shfl_down_sync(0xffffffffu, v, ofs);
        if (lane == 0) y_s[b] = v;
    }
    __syncthreads();

    if (t < BB) {
        float gt = 0.f;
#pragma unroll
        for (int k = 0; k < KK; k++) gt += sg_s[k] * d_tk[k];
        out[t] = (y_s[t] + gt) * (1.0f / (float)LL) + d_misc[0] + d_misc[1];
    }
}

// ============================================================
extern "C" void kernel_launch(void* const* d_in, const int* in_sizes, int n_in,
                              void* d_out, int out_size) {
    const float* x   = (const float*)d_in[0];
    const float* A   = (const float*)d_in[1];
    const float* W1  = (const float*)d_in[2];
    const float* b1  = (const float*)d_in[3];
    const float* W2  = (const float*)d_in[4];
    const float* b2  = (const float*)d_in[5];
    const float* cw  = (const float*)d_in[6];
    const float* cb  = (const float*)d_in[7];
    const float* fw  = (const float*)d_in[8];
    const float* fb  = (const float*)d_in[9];
    float* out = (float*)d_out;

    kA<<<577, 256>>>(A, x, W1, b1, W2, b2, cw, cb, fw, fb);
    kB<<<dim3(4, RC2), 256>>>(A);
    kC<<<NCB, 256>>>();
    kD<<<1, 256>>>(out);
}